// round 8
// baseline (speedup 1.0000x reference)
#include <cuda_runtime.h>
#include <math.h>

#define N_BATCH 32
#define C_IN    256
#define C_SQ    64
#define HW      12544              // 112*112
#define HW4     3136               // float4 per plane
#define PLANES  (N_BATCH * C_IN)   // 8192
#define TPB     448                // 448 * 7 == 3136 exactly
#define VPT     7                  // float4 per thread

// Scratch (no allocations allowed). Zero-initialized; counters self-reset.
__device__ float    g_pool[PLANES];
__device__ float    g_gate[PLANES];
__device__ unsigned g_cnt_pool[N_BATCH];
__device__ unsigned g_cnt_scale[N_BATCH];
__device__ unsigned g_flag[N_BATCH];

__device__ __forceinline__ unsigned ld_acquire_gpu(const unsigned* p) {
    unsigned v;
    asm volatile("ld.acquire.gpu.u32 %0, [%1];" : "=r"(v) : "l"(p) : "memory");
    return v;
}

// ---------------------------------------------------------------------------
// Single fused kernel: one block per (n,c) plane.
// Plane data stays register-resident across pool -> gate -> scale, so x is
// read from DRAM exactly ONCE (822 MB total traffic instead of 1233 MB).
// ---------------------------------------------------------------------------
__global__ __launch_bounds__(TPB, 2) void se_fused_kernel(
    const float* __restrict__ x,
    float*       __restrict__ out,
    const float* __restrict__ w_reduce,   // [C_SQ, C_IN]
    const float* __restrict__ b_reduce,   // [C_SQ]
    const float* __restrict__ w_expand,   // [C_IN, C_SQ]
    const float* __restrict__ b_expand)   // [C_IN]
{
    const int plane = blockIdx.x;
    const int n     = plane >> 8;
    const int tid   = threadIdx.x;
    const int lane  = tid & 31;
    const int wid   = tid >> 5;

    const float4* p = reinterpret_cast<const float4*>(x   + (size_t)plane * HW);
    float4*       q = reinterpret_cast<float4*>(out       + (size_t)plane * HW);

    // ---- 1) load the whole plane into registers (streaming, evict-first) ----
    float4 v[VPT];
    #pragma unroll
    for (int i = 0; i < VPT; i++)
        v[i] = __ldcs(&p[tid + i * TPB]);

    // ---- 2) block reduction -> plane mean ----
    float sum = 0.0f;
    #pragma unroll
    for (int i = 0; i < VPT; i++)
        sum += (v[i].x + v[i].y) + (v[i].z + v[i].w);

    #pragma unroll
    for (int off = 16; off > 0; off >>= 1)
        sum += __shfl_down_sync(0xFFFFFFFFu, sum, off);

    __shared__ float warp_sums[TPB / 32];   // 14
    __shared__ int   s_amlast;
    if (lane == 0) warp_sums[wid] = sum;
    __syncthreads();

    if (tid == 0) {
        float s = 0.0f;
        #pragma unroll
        for (int w = 0; w < TPB / 32; w++) s += warp_sums[w];
        g_pool[plane] = s * (1.0f / (float)HW);
        __threadfence();                                   // release the mean
        unsigned old = atomicAdd(&g_cnt_pool[n], 1u);
        s_amlast = (old == (unsigned)(C_IN - 1));
    }
    __syncthreads();

    // ---- 3) last arriver of this batch computes the MLP -> gates ----
    if (s_amlast) {
        __shared__ float s_in[C_IN];
        __shared__ float s_red[C_SQ];

        if (tid < C_IN) s_in[tid] = __ldcg(&g_pool[n * C_IN + tid]);
        __syncthreads();

        if (tid < C_SQ) {
            float a0 = b_reduce[tid], a1 = 0.f, a2 = 0.f, a3 = 0.f;
            const float* wr = w_reduce + tid * C_IN;
            #pragma unroll 4
            for (int k = 0; k < C_IN; k += 4) {
                a0 = fmaf(wr[k + 0], s_in[k + 0], a0);
                a1 = fmaf(wr[k + 1], s_in[k + 1], a1);
                a2 = fmaf(wr[k + 2], s_in[k + 2], a2);
                a3 = fmaf(wr[k + 3], s_in[k + 3], a3);
            }
            s_red[tid] = fmaxf((a0 + a1) + (a2 + a3), 0.0f);
        }
        __syncthreads();

        if (tid < C_IN) {
            float acc = b_expand[tid];
            const float* we = w_expand + tid * C_SQ;
            #pragma unroll 8
            for (int k = 0; k < C_SQ; k++)
                acc = fmaf(we[k], s_red[k], acc);
            g_gate[n * C_IN + tid] = 1.0f / (1.0f + __expf(-acc));
        }
        __syncthreads();
        if (tid == 0) {
            __threadfence();                               // release gates
            atomicExch(&g_flag[n], 1u);
        }
    }

    // ---- 4) wait for this batch's gates ----
    if (tid == 0) {
        while (ld_acquire_gpu(&g_flag[n]) == 0u)
            __nanosleep(64);
    }
    __syncthreads();

    const float g = __ldcg(&g_gate[plane]);

    // ---- 5) scale the register-resident plane and stream it out ----
    #pragma unroll
    for (int i = 0; i < VPT; i++) {
        v[i].x *= g; v[i].y *= g; v[i].z *= g; v[i].w *= g;
        __stcs(&q[tid + i * TPB], v[i]);
    }

    // ---- 6) self-reset for graph replay ----
    if (tid == 0) {
        unsigned old = atomicAdd(&g_cnt_scale[n], 1u);
        if (old == (unsigned)(C_IN - 1)) {                 // last scaler of batch
            atomicExch(&g_cnt_pool[n], 0u);
            atomicExch(&g_cnt_scale[n], 0u);
            atomicExch(&g_flag[n], 0u);
        }
    }
}

// ---------------------------------------------------------------------------
extern "C" void kernel_launch(void* const* d_in, const int* in_sizes, int n_in,
                              void* d_out, int out_size)
{
    const float* x        = (const float*)d_in[0];
    const float* w_reduce = (const float*)d_in[1];
    const float* b_reduce = (const float*)d_in[2];
    const float* w_expand = (const float*)d_in[3];
    const float* b_expand = (const float*)d_in[4];
    float* out = (float*)d_out;

    se_fused_kernel<<<PLANES, TPB>>>(x, out, w_reduce, b_reduce,
                                     w_expand, b_expand);
}

// round 10
// speedup vs baseline: 3.9753x; 3.9753x over previous
#include <cuda_runtime.h>
#include <math.h>

#define N_BATCH 32
#define C_IN    256
#define C_SQ    64
#define HW      12544              // 112*112
#define HW4     3136               // HW/4 float4 per plane
#define PLANES  (N_BATCH * C_IN)   // 8192
#define TPB     448                // 448 * 7 == 3136 exactly
#define VPT     7                  // float4 per thread (scale kernel)

// Scratch (no allocations allowed)
__device__ float g_pool[PLANES];
__device__ float g_gate[PLANES];

// ---------------------------------------------------------------------------
// Kernel 1: global average pool. One block per (n,c) plane, 256 threads,
// strided float4 loop (best measured config: ~61us @ 86% DRAM).
// ---------------------------------------------------------------------------
__global__ __launch_bounds__(256) void se_pool_kernel(
    const float* __restrict__ x)
{
    const int plane = blockIdx.x;
    const float4* p = reinterpret_cast<const float4*>(x + (size_t)plane * HW);

    float sum = 0.0f;
    #pragma unroll 4
    for (int i = threadIdx.x; i < HW4; i += 256) {
        float4 v = p[i];
        sum += (v.x + v.y) + (v.z + v.w);
    }

    #pragma unroll
    for (int off = 16; off > 0; off >>= 1)
        sum += __shfl_down_sync(0xFFFFFFFFu, sum, off);

    __shared__ float warp_sums[8];
    const int lane = threadIdx.x & 31;
    const int wid  = threadIdx.x >> 5;
    if (lane == 0) warp_sums[wid] = sum;
    __syncthreads();

    if (wid == 0) {
        float s = (lane < 8) ? warp_sums[lane] : 0.0f;
        #pragma unroll
        for (int off = 4; off > 0; off >>= 1)
            s += __shfl_down_sync(0xFFFFFFFFu, s, off);
        if (lane == 0)
            g_pool[plane] = s * (1.0f / (float)HW);
    }
}

// ---------------------------------------------------------------------------
// Kernel 2: MLP. One block per batch element, plain launch (tiny, ~2us).
// Calls the PDL trigger so the dependent scale grid may launch early.
// ---------------------------------------------------------------------------
__global__ __launch_bounds__(256) void se_mlp_kernel(
    const float* __restrict__ w_reduce,   // [C_SQ, C_IN]
    const float* __restrict__ b_reduce,   // [C_SQ]
    const float* __restrict__ w_expand,   // [C_IN, C_SQ]
    const float* __restrict__ b_expand)   // [C_IN]
{
    const int n   = blockIdx.x;
    const int tid = threadIdx.x;

    __shared__ float s_in[C_IN];
    __shared__ float s_red[C_SQ];

    s_in[tid] = g_pool[n * C_IN + tid];
    __syncthreads();

    if (tid < C_SQ) {
        float acc = b_reduce[tid];
        const float* wr = w_reduce + tid * C_IN;
        #pragma unroll 8
        for (int c = 0; c < C_IN; c++)
            acc = fmaf(wr[c], s_in[c], acc);
        s_red[tid] = fmaxf(acc, 0.0f);
    }
    __syncthreads();

    float acc = b_expand[tid];
    const float* we = w_expand + tid * C_SQ;
    #pragma unroll 8
    for (int k = 0; k < C_SQ; k++)
        acc = fmaf(we[k], s_red[k], acc);

    g_gate[n * C_IN + tid] = 1.0f / (1.0f + __expf(-acc));

    cudaTriggerProgrammaticLaunchCompletion();
}

// ---------------------------------------------------------------------------
// Kernel 3: out = gate[plane] * x. PDL secondary: front-batch the 7 x-plane
// loads BEFORE cudaGridDependencySynchronize (x is a kernel input, not a
// product of pool/mlp), so the load ramp overlaps the previous grids' drain.
// Reversed plane order for L2 tail reuse; streaming stores.
// ---------------------------------------------------------------------------
__global__ __launch_bounds__(TPB) void se_scale_kernel(
    const float* __restrict__ x,
    float*       __restrict__ out)
{
    const int plane = (PLANES - 1) - blockIdx.x;

    const float4* p = reinterpret_cast<const float4*>(x   + (size_t)plane * HW);
    float4*       q = reinterpret_cast<float4*>(out       + (size_t)plane * HW);

    float4 v[VPT];
    #pragma unroll
    for (int i = 0; i < VPT; i++)
        v[i] = p[threadIdx.x + i * TPB];

    cudaGridDependencySynchronize();      // gates now guaranteed visible

    const float g = __ldg(&g_gate[plane]);

    #pragma unroll
    for (int i = 0; i < VPT; i++) {
        v[i].x *= g; v[i].y *= g; v[i].z *= g; v[i].w *= g;
        __stcs(&q[threadIdx.x + i * TPB], v[i]);
    }
}

// ---------------------------------------------------------------------------
extern "C" void kernel_launch(void* const* d_in, const int* in_sizes, int n_in,
                              void* d_out, int out_size)
{
    const float* x        = (const float*)d_in[0];
    const float* w_reduce = (const float*)d_in[1];
    const float* b_reduce = (const float*)d_in[2];
    const float* w_expand = (const float*)d_in[3];
    const float* b_expand = (const float*)d_in[4];
    float* out = (float*)d_out;

    se_pool_kernel<<<PLANES, 256>>>(x);
    se_mlp_kernel<<<N_BATCH, 256>>>(w_reduce, b_reduce, w_expand, b_expand);

    // Scale: the only PDL secondary — its launch/load ramp overlaps the
    // MLP (and the pool drain behind it).
    {
        cudaLaunchConfig_t cfg = {};
        cfg.gridDim  = dim3(PLANES, 1, 1);
        cfg.blockDim = dim3(TPB, 1, 1);
        cfg.stream   = 0;
        cudaLaunchAttribute attr[1];
        attr[0].id = cudaLaunchAttributeProgrammaticStreamSerialization;
        attr[0].val.programmaticStreamSerializationAllowed = 1;
        cfg.attrs    = attr;
        cfg.numAttrs = 1;
        cudaLaunchKernelEx(&cfg, se_scale_kernel, x, out);
    }
}